// round 5
// baseline (speedup 1.0000x reference)
#include <cuda_runtime.h>
#include <cstdint>

// ============================================================================
// out[4096,4096] = ((x - xz)*sx) @ ((y - yz)*sy)
// Exact int8 GEMM (mma.sync m16n8k32 s8) + rank-1 zero-point correction.
// No tcgen05: harness lowers PTX to compute_103 (non-'a'), which rejects it.
// ============================================================================

#define MDIM 4096

static constexpr double X_SCALE = 0.03, X_ZP = -66.0;
static constexpr double Y_SCALE = 0.025, Y_ZP = 160.0;

// GEMM tiling
static constexpr int BM = 128, BN = 256, BK = 64, STAGES = 4;
static constexpr int NKT = MDIM / BK;  // 64
static constexpr int ROWB = 80;        // smem row stride (bytes) for 64B of data
static constexpr int A_STAGE = BM * ROWB;            // 10240
static constexpr int B_STAGE = BN * ROWB;            // 20480
static constexpr int STAGE_BYTES = A_STAGE + B_STAGE; // 30720
static constexpr int SMEM_TOTAL = STAGES * STAGE_BYTES; // 122880

// Scratch (device globals: allocation-free per harness rules)
__device__ char  g_x8 [(size_t)MDIM * MDIM];  // x as s8 (exact)
__device__ char  g_y8t[(size_t)MDIM * MDIM];  // (y-128)^T as s8, [N,K]
__device__ float g_rowsum[MDIM];              // sum_k x[m,k]   (exact integer)
__device__ float g_colsum[MDIM];              // sum_k y[k,n]   (exact integer)

// ---------------------------------------------------------------------------
// PTX helpers
// ---------------------------------------------------------------------------
__device__ __forceinline__ uint32_t smem_u32(const void* p) {
    uint32_t a;
    asm("{ .reg .u64 t; cvta.to.shared.u64 t, %1; cvt.u32.u64 %0, t; }"
        : "=r"(a) : "l"(p));
    return a;
}
__device__ __forceinline__ void cp_async16(uint32_t s, const void* g) {
    asm volatile("cp.async.cg.shared.global [%0], [%1], 16;" :: "r"(s), "l"(g));
}
#define CP_COMMIT() asm volatile("cp.async.commit_group;")
#define CP_WAIT2()  asm volatile("cp.async.wait_group 2;")

__device__ __forceinline__ void ldmatrix_x4(uint32_t* r, uint32_t addr) {
    asm volatile("ldmatrix.sync.aligned.m8n8.x4.shared.b16 {%0,%1,%2,%3}, [%4];"
                 : "=r"(r[0]), "=r"(r[1]), "=r"(r[2]), "=r"(r[3]) : "r"(addr));
}
__device__ __forceinline__ void ldmatrix_x2(uint32_t* r, uint32_t addr) {
    asm volatile("ldmatrix.sync.aligned.m8n8.x2.shared.b16 {%0,%1}, [%2];"
                 : "=r"(r[0]), "=r"(r[1]) : "r"(addr));
}
__device__ __forceinline__ void mma_s8(int* d, const uint32_t* a, const uint32_t* b) {
    asm volatile(
        "mma.sync.aligned.m16n8k32.row.col.s32.s8.s8.s32 "
        "{%0,%1,%2,%3}, {%4,%5,%6,%7}, {%8,%9}, {%0,%1,%2,%3};"
        : "+r"(d[0]), "+r"(d[1]), "+r"(d[2]), "+r"(d[3])
        : "r"(a[0]), "r"(a[1]), "r"(a[2]), "r"(a[3]), "r"(b[0]), "r"(b[1]));
}

// ---------------------------------------------------------------------------
// Preprocessing
// ---------------------------------------------------------------------------
__global__ __launch_bounds__(256) void convert_x_kernel(const float* __restrict__ x) {
    int row = blockIdx.x;
    const float4* xr = (const float4*)(x + (size_t)row * MDIM);
    uchar4* xo = (uchar4*)(g_x8 + (size_t)row * MDIM);
    float s = 0.f;
#pragma unroll
    for (int q = 0; q < 4; q++) {
        int i = q * 256 + threadIdx.x;
        float4 v = xr[i];
        s += (v.x + v.y) + (v.z + v.w);
        uchar4 o;
        o.x = (unsigned char)(int)v.x;  // bit pattern of s8 value (exact)
        o.y = (unsigned char)(int)v.y;
        o.z = (unsigned char)(int)v.z;
        o.w = (unsigned char)(int)v.w;
        xo[i] = o;
    }
    __shared__ float red[256];
    red[threadIdx.x] = s;
    __syncthreads();
    for (int st = 128; st > 0; st >>= 1) {
        if (threadIdx.x < st) red[threadIdx.x] += red[threadIdx.x + st];
        __syncthreads();
    }
    if (threadIdx.x == 0) g_rowsum[row] = red[0];
}

// yT[n][k] = (s8)(y[k][n] - 128)
__global__ __launch_bounds__(256) void transpose_y_kernel(const float* __restrict__ y) {
    __shared__ float tile[32][33];
    int n0 = blockIdx.x * 32, k0 = blockIdx.y * 32;
    int tx = threadIdx.x & 31, ty = threadIdx.x >> 5;  // (32, 8)
#pragma unroll
    for (int j = 0; j < 4; j++)
        tile[ty + 8 * j][tx] = y[(size_t)(k0 + ty + 8 * j) * MDIM + n0 + tx];
    __syncthreads();
    int n = threadIdx.x >> 3, kc = threadIdx.x & 7;
    uchar4 o;
    o.x = (unsigned char)((int)tile[kc * 4 + 0][n] - 128);
    o.y = (unsigned char)((int)tile[kc * 4 + 1][n] - 128);
    o.z = (unsigned char)((int)tile[kc * 4 + 2][n] - 128);
    o.w = (unsigned char)((int)tile[kc * 4 + 3][n] - 128);
    *(uchar4*)(g_y8t + (size_t)(n0 + n) * MDIM + k0 + kc * 4) = o;
}

__global__ __launch_bounds__(256) void colsum_y_kernel(const float* __restrict__ y) {
    int n = blockIdx.x * 256 + threadIdx.x;
    int kbase = blockIdx.y * 256;
    float s = 0.f;
#pragma unroll 8
    for (int k = 0; k < 256; k++) s += y[(size_t)(kbase + k) * MDIM + n];
    atomicAdd(&g_colsum[n], s);  // integer-valued: exact & order-independent
}

// ---------------------------------------------------------------------------
// GEMM: 128x256 CTA tile, 512 thr (16 warps, 2x8 grid -> warp tile 64x32),
// BK=64, 4-stage cp.async pipeline, mma.sync m16n8k32 s8
// ---------------------------------------------------------------------------
__global__ __launch_bounds__(512, 1) void gemm_kernel(float* __restrict__ out) {
    extern __shared__ __align__(128) char smem[];
    const uint32_t sbase = smem_u32(smem);
    const int tid = threadIdx.x, lane = tid & 31, wid = tid >> 5;
    const int wm = (wid >> 3) * 64;   // warp m-offset (0 or 64)
    const int wn = (wid & 7) * 32;    // warp n-offset (0..224)
    const int m0 = blockIdx.y * BM, n0 = blockIdx.x * BN;

    int acc[4][4][4];
#pragma unroll
    for (int i = 0; i < 4; i++)
#pragma unroll
        for (int j = 0; j < 4; j++)
#pragma unroll
            for (int v = 0; v < 4; v++) acc[i][j][v] = 0;

    const char* gAbase = g_x8  + (size_t)m0 * MDIM;
    const char* gBbase = g_y8t + (size_t)n0 * MDIM;

    auto load_tile = [&](int kt, int s) {
        uint32_t sA = sbase + s * STAGE_BYTES;
        uint32_t sB = sA + A_STAGE;
        const char* gA = gAbase + kt * BK;
        const char* gB = gBbase + kt * BK;
        {   // A: 128 rows x 4 x 16B = 512 chunks, one per thread
            int row = tid >> 2, ch = tid & 3;
            cp_async16(sA + row * ROWB + ch * 16,
                       gA + (size_t)row * MDIM + ch * 16);
        }
#pragma unroll
        for (int q = 0; q < 2; q++) {  // B: 256 rows x 4 chunks = 1024
            int idx = tid + q * 512;
            int row = idx >> 2, ch = idx & 3;
            cp_async16(sB + row * ROWB + ch * 16,
                       gB + (size_t)row * MDIM + ch * 16);
        }
    };

    // ldmatrix lane addressing
    const int rA = (lane & 7) + ((lane >> 3) & 1) * 8;  // 0..15
    const int cA = lane >> 4;                           // 0/1 (16B chunk)
    const int rB = lane & 7;
    const int cB = (lane >> 3) & 1;

    // Prologue: stages 0..2 in flight
#pragma unroll
    for (int s = 0; s < STAGES - 1; s++) { load_tile(s, s); CP_COMMIT(); }

#pragma unroll 1
    for (int kt = 0; kt < NKT; ++kt) {
        const int s = kt & 3;
        CP_WAIT2();
        __syncthreads();
        const int next = kt + STAGES - 1;
        if (next < NKT) load_tile(next, next & 3);
        CP_COMMIT();  // exactly one group per iteration (possibly empty)

        const uint32_t aW = sbase + s * STAGE_BYTES + (wm + rA) * ROWB + cA * 16;
        const uint32_t bW = sbase + s * STAGE_BYTES + A_STAGE +
                            (wn + rB) * ROWB + cB * 16;
#pragma unroll
        for (int ks = 0; ks < 2; ks++) {
            uint32_t a[4][4], b[4][2];
#pragma unroll
            for (int i = 0; i < 4; i++)
                ldmatrix_x4(a[i], aW + i * 16 * ROWB + ks * 32);
#pragma unroll
            for (int j = 0; j < 4; j++)
                ldmatrix_x2(b[j], bW + j * 8 * ROWB + ks * 32);
#pragma unroll
            for (int i = 0; i < 4; i++)
#pragma unroll
                for (int j = 0; j < 4; j++)
                    mma_s8(acc[i][j], a[i], b[j]);
        }
    }

    // Epilogue: out = S*P + S*(128-yz)*rowsum_x[m] - S*xz*colsum_y[n] + S*K*xz*yz
    constexpr double Sd = X_SCALE * Y_SCALE;
    const float Sc     = (float)Sd;
    const float Crow   = (float)(Sd * (128.0 - Y_ZP));
    const float Ccol   = (float)(-Sd * X_ZP);
    const float Cconst = (float)(Sd * (double)MDIM * X_ZP * Y_ZP);

    const int rr = lane >> 2;          // 0..7
    const int cc = (lane & 3) * 2;     // 0,2,4,6

    float rowC[4][2];
#pragma unroll
    for (int i = 0; i < 4; i++) {
        int r = m0 + wm + i * 16 + rr;
        rowC[i][0] = Crow * g_rowsum[r]     + Cconst;
        rowC[i][1] = Crow * g_rowsum[r + 8] + Cconst;
    }
    float colC[4][2];
#pragma unroll
    for (int j = 0; j < 4; j++) {
        int c = n0 + wn + j * 8 + cc;
        colC[j][0] = Ccol * g_colsum[c];
        colC[j][1] = Ccol * g_colsum[c + 1];
    }

#pragma unroll
    for (int i = 0; i < 4; i++) {
#pragma unroll
        for (int j = 0; j < 4; j++) {
            size_t r = (size_t)(m0 + wm + i * 16 + rr);
            size_t c = (size_t)(n0 + wn + j * 8 + cc);
            float2 v0, v1;
            v0.x = Sc * (float)acc[i][j][0] + rowC[i][0] + colC[j][0];
            v0.y = Sc * (float)acc[i][j][1] + rowC[i][0] + colC[j][1];
            v1.x = Sc * (float)acc[i][j][2] + rowC[i][1] + colC[j][0];
            v1.y = Sc * (float)acc[i][j][3] + rowC[i][1] + colC[j][1];
            *(float2*)(out + r * MDIM + c)       = v0;
            *(float2*)(out + (r + 8) * MDIM + c) = v1;
        }
    }
}

// ---------------------------------------------------------------------------
// Launch
// ---------------------------------------------------------------------------
extern "C" void kernel_launch(void* const* d_in, const int* in_sizes, int n_in,
                              void* d_out, int out_size) {
    const float* x = (const float*)d_in[0];  // [M,K]
    const float* y = (const float*)d_in[1];  // [K,N]
    float* out = (float*)d_out;

    cudaFuncSetAttribute(gemm_kernel,
                         cudaFuncAttributeMaxDynamicSharedMemorySize, SMEM_TOTAL);

    void* csym = nullptr;
    cudaGetSymbolAddress(&csym, g_colsum);
    cudaMemsetAsync(csym, 0, MDIM * sizeof(float), 0);

    convert_x_kernel<<<MDIM, 256>>>(x);
    transpose_y_kernel<<<dim3(MDIM / 32, MDIM / 32), 256>>>(y);
    colsum_y_kernel<<<dim3(MDIM / 256, 16), 256>>>(y);
    gemm_kernel<<<dim3(MDIM / BN, MDIM / BM), 512, SMEM_TOTAL>>>(out);
}

// round 6
// speedup vs baseline: 1.1322x; 1.1322x over previous
#include <cuda_runtime.h>
#include <cstdint>

// ============================================================================
// out[4096,4096] = ((x - xz)*sx) @ ((y - yz)*sy)
// Exact int8 GEMM (mma.sync m16n8k32 s8) + rank-1 zero-point correction.
// tcgen05 unavailable: harness lowers PTX to compute_103 (non-'a').
// R6: persistent round-robin tiles (kills wave quantization), 2 CTAs/SM,
//     cross-tile flattened cp.async pipeline, cheaper preprocessing.
// ============================================================================

#define MDIM 4096

static constexpr double X_SCALE = 0.03, X_ZP = -66.0;
static constexpr double Y_SCALE = 0.025, Y_ZP = 160.0;

// GEMM tiling
static constexpr int BM = 128, BN = 64, BK = 64, STAGES = 4;
static constexpr int ROWB = 80;                       // 64B data + 16B pad
static constexpr int A_STAGE = BM * ROWB;             // 10240
static constexpr int B_STAGE = BN * ROWB;             // 5120
static constexpr int STAGE_BYTES = A_STAGE + B_STAGE; // 15360
static constexpr int SMEM_TOTAL = STAGES * STAGE_BYTES; // 61440 (x2 CTAs = 120KB)
static constexpr int NT_N = MDIM / BN;                // 64
static constexpr int NTILES = (MDIM / BM) * NT_N;     // 2048
static constexpr int KITER = MDIM / BK;               // 64

// Scratch (device globals: allocation-free per harness rules)
__device__ char  g_x8 [(size_t)MDIM * MDIM];  // x as s8 (exact)
__device__ char  g_y8t[(size_t)MDIM * MDIM];  // (y-128)^T as s8, [N,K]
__device__ float g_rowsum[MDIM];              // sum_k x[m,k]  (exact integer)
__device__ float g_colsum[MDIM];              // sum_k y[k,n]  (exact integer)

// ---------------------------------------------------------------------------
// PTX helpers
// ---------------------------------------------------------------------------
__device__ __forceinline__ uint32_t smem_u32(const void* p) {
    uint32_t a;
    asm("{ .reg .u64 t; cvta.to.shared.u64 t, %1; cvt.u32.u64 %0, t; }"
        : "=r"(a) : "l"(p));
    return a;
}
__device__ __forceinline__ void cp_async16(uint32_t s, const void* g) {
    asm volatile("cp.async.cg.shared.global [%0], [%1], 16;" :: "r"(s), "l"(g));
}
#define CP_COMMIT() asm volatile("cp.async.commit_group;")
#define CP_WAIT2()  asm volatile("cp.async.wait_group 2;")

__device__ __forceinline__ void ldmatrix_x4(uint32_t* r, uint32_t addr) {
    asm volatile("ldmatrix.sync.aligned.m8n8.x4.shared.b16 {%0,%1,%2,%3}, [%4];"
                 : "=r"(r[0]), "=r"(r[1]), "=r"(r[2]), "=r"(r[3]) : "r"(addr));
}
__device__ __forceinline__ void mma_s8(int* d, const uint32_t* a, const uint32_t* b) {
    asm volatile(
        "mma.sync.aligned.m16n8k32.row.col.s32.s8.s8.s32 "
        "{%0,%1,%2,%3}, {%4,%5,%6,%7}, {%8,%9}, {%0,%1,%2,%3};"
        : "+r"(d[0]), "+r"(d[1]), "+r"(d[2]), "+r"(d[3])
        : "r"(a[0]), "r"(a[1]), "r"(a[2]), "r"(a[3]), "r"(b[0]), "r"(b[1]));
}

// ---------------------------------------------------------------------------
// Preprocessing
// ---------------------------------------------------------------------------
__global__ __launch_bounds__(256) void convert_x_kernel(const float* __restrict__ x) {
    int row = blockIdx.x;
    const float4* xr = (const float4*)(x + (size_t)row * MDIM);
    uchar4* xo = (uchar4*)(g_x8 + (size_t)row * MDIM);
    float s = 0.f;
#pragma unroll
    for (int q = 0; q < 4; q++) {
        int i = q * 256 + threadIdx.x;
        float4 v = xr[i];
        s += (v.x + v.y) + (v.z + v.w);
        uchar4 o;
        o.x = (unsigned char)(int)v.x;  // s8 bit pattern (exact)
        o.y = (unsigned char)(int)v.y;
        o.z = (unsigned char)(int)v.z;
        o.w = (unsigned char)(int)v.w;
        xo[i] = o;
    }
    __shared__ float red[256];
    red[threadIdx.x] = s;
    __syncthreads();
    for (int st = 128; st > 0; st >>= 1) {
        if (threadIdx.x < st) red[threadIdx.x] += red[threadIdx.x + st];
        __syncthreads();
    }
    if (threadIdx.x == 0) g_rowsum[row] = red[0];
}

// y8t[n][k] = (s8)(y[k][n] - 128); 64x64 tiles, 16B coalesced stores
__global__ __launch_bounds__(256) void transpose_y_kernel(const float* __restrict__ y) {
    __shared__ float tile[64][65];
    int n0 = blockIdx.x * 64, k0 = blockIdx.y * 64;
    int tid = threadIdx.x;
    int col = tid & 63, r4 = tid >> 6;  // 4 rows per pass
#pragma unroll
    for (int p = 0; p < 16; p++) {
        int row = p * 4 + r4;
        tile[row][col] = y[(size_t)(k0 + row) * MDIM + n0 + col];
    }
    __syncthreads();
    int n = tid >> 2, kc = tid & 3;  // each thread: 16 k for one n
    uchar4 o[4];
#pragma unroll
    for (int q = 0; q < 4; q++) {
        int k = kc * 16 + q * 4;
        o[q].x = (unsigned char)((int)tile[k + 0][n] - 128);
        o[q].y = (unsigned char)((int)tile[k + 1][n] - 128);
        o[q].z = (unsigned char)((int)tile[k + 2][n] - 128);
        o[q].w = (unsigned char)((int)tile[k + 3][n] - 128);
    }
    *(uint4*)(g_y8t + (size_t)(n0 + n) * MDIM + k0 + kc * 16) = *(uint4*)o;
}

// colsum_y[n] = sum_k y[k][n] = rowsum(y8t[n]) + 128*K ; dp4a over int8 rows
__global__ __launch_bounds__(256) void colsum_kernel() {
    int n = blockIdx.x;
    const int* r = (const int*)(g_y8t + (size_t)n * MDIM);  // 1024 words
    int s = 0;
#pragma unroll
    for (int q = 0; q < 4; q++) s = __dp4a(r[q * 256 + threadIdx.x], 0x01010101, s);
    __shared__ int red[256];
    red[threadIdx.x] = s;
    __syncthreads();
    for (int st = 128; st > 0; st >>= 1) {
        if (threadIdx.x < st) red[threadIdx.x] += red[threadIdx.x + st];
        __syncthreads();
    }
    if (threadIdx.x == 0) g_colsum[n] = (float)(red[0] + 128 * MDIM);
}

// ---------------------------------------------------------------------------
// GEMM: persistent workers, CTA tile 128x64, 256 thr (8 warps, 4x2 grid,
// warp tile 32x32), BK=64, 4-stage cross-tile cp.async pipeline
// ---------------------------------------------------------------------------
__global__ __launch_bounds__(256, 2) void gemm_kernel(float* __restrict__ out,
                                                      int nworkers) {
    extern __shared__ __align__(128) char smem[];
    const uint32_t sbase = smem_u32(smem);
    const int tid = threadIdx.x, lane = tid & 31, wid = tid >> 5;
    const int worker = blockIdx.x;
    const int wm = (wid >> 1) * 32;   // warp m-offset 0..96
    const int wn = (wid & 1) * 32;    // warp n-offset 0/32

    const int cnt = (worker < NTILES) ? (NTILES - 1 - worker) / nworkers + 1 : 0;
    const int total = cnt * KITER;
    if (total == 0) return;

    // per-thread load slots (3 x 16B per stage)
    const int lrow = tid >> 2, lch = (tid & 3) * 16;

    auto load_g = [&](int g) {
        int t = worker + (g >> 6) * nworkers;   // tile id
        int kt = g & (KITER - 1);
        const char* gA = g_x8  + (size_t)((t >> 6) * BM) * MDIM + kt * BK;
        const char* gB = g_y8t + (size_t)((t & (NT_N - 1)) * BN) * MDIM + kt * BK;
        uint32_t sA = sbase + (g & 3) * STAGE_BYTES;
        uint32_t sB = sA + A_STAGE;
        cp_async16(sA + lrow * ROWB + lch, gA + (size_t)lrow * MDIM + lch);
        cp_async16(sA + (lrow + 64) * ROWB + lch,
                   gA + (size_t)(lrow + 64) * MDIM + lch);
        cp_async16(sB + lrow * ROWB + lch, gB + (size_t)lrow * MDIM + lch);
    };

    // ldmatrix lane addressing (identical fragment layout to R5-passing code)
    const int rA = (lane & 7) + ((lane >> 3) & 1) * 8;  // 0..15
    const int cA = (lane >> 4) * 16;                    // 0/16
    const int rB = (lane & 7) + (lane >> 4) * 8;        // j-pair packing
    const int cB = ((lane >> 3) & 1) * 16;

    int acc[2][4][4];
#pragma unroll
    for (int i = 0; i < 2; i++)
#pragma unroll
        for (int j = 0; j < 4; j++)
#pragma unroll
            for (int v = 0; v < 4; v++) acc[i][j][v] = 0;

    // Epilogue constants
    constexpr double Sd = X_SCALE * Y_SCALE;
    const float Sc     = (float)Sd;
    const float Crow   = (float)(Sd * (128.0 - Y_ZP));
    const float Ccol   = (float)(-Sd * X_ZP);
    const float Cconst = (float)(Sd * (double)MDIM * X_ZP * Y_ZP);
    const int rr = lane >> 2, cc = (lane & 3) * 2;

#pragma unroll
    for (int g = 0; g < STAGES - 1; g++) { load_g(g); CP_COMMIT(); }

#pragma unroll 1
    for (int g = 0; g < total; ++g) {
        CP_WAIT2();
        __syncthreads();
        if (g + 3 < total) load_g(g + 3);
        CP_COMMIT();  // exactly one group per iteration

        const uint32_t aW = sbase + (g & 3) * STAGE_BYTES + (wm + rA) * ROWB + cA;
        const uint32_t bW = sbase + (g & 3) * STAGE_BYTES + A_STAGE +
                            (wn + rB) * ROWB + cB;
#pragma unroll
        for (int ks = 0; ks < 2; ks++) {
            uint32_t a0[4], a1[4], b0[4], b1[4];
            ldmatrix_x4(a0, aW + ks * 32);
            ldmatrix_x4(a1, aW + 16 * ROWB + ks * 32);
            ldmatrix_x4(b0, bW + ks * 32);            // j = 0,1
            ldmatrix_x4(b1, bW + 16 * ROWB + ks * 32);// j = 2,3
            mma_s8(acc[0][0], a0, b0 + 0);
            mma_s8(acc[0][1], a0, b0 + 2);
            mma_s8(acc[0][2], a0, b1 + 0);
            mma_s8(acc[0][3], a0, b1 + 2);
            mma_s8(acc[1][0], a1, b0 + 0);
            mma_s8(acc[1][1], a1, b0 + 2);
            mma_s8(acc[1][2], a1, b1 + 0);
            mma_s8(acc[1][3], a1, b1 + 2);
        }

        if ((g & (KITER - 1)) == KITER - 1) {
            // Epilogue (register-only; no smem, no sync)
            int t = worker + (g >> 6) * nworkers;
            int m0 = (t >> 6) * BM, n0 = (t & (NT_N - 1)) * BN;
            float rowC[2][2], colC[4][2];
#pragma unroll
            for (int i = 0; i < 2; i++) {
                int r = m0 + wm + i * 16 + rr;
                rowC[i][0] = Crow * g_rowsum[r]     + Cconst;
                rowC[i][1] = Crow * g_rowsum[r + 8] + Cconst;
            }
#pragma unroll
            for (int j = 0; j < 4; j++) {
                int c = n0 + wn + j * 8 + cc;
                colC[j][0] = Ccol * g_colsum[c];
                colC[j][1] = Ccol * g_colsum[c + 1];
            }
#pragma unroll
            for (int i = 0; i < 2; i++) {
#pragma unroll
                for (int j = 0; j < 4; j++) {
                    size_t r = (size_t)(m0 + wm + i * 16 + rr);
                    size_t c = (size_t)(n0 + wn + j * 8 + cc);
                    float2 v0, v1;
                    v0.x = Sc * (float)acc[i][j][0] + rowC[i][0] + colC[j][0];
                    v0.y = Sc * (float)acc[i][j][1] + rowC[i][0] + colC[j][1];
                    v1.x = Sc * (float)acc[i][j][2] + rowC[i][1] + colC[j][0];
                    v1.y = Sc * (float)acc[i][j][3] + rowC[i][1] + colC[j][1];
                    *(float2*)(out + r * MDIM + c)       = v0;
                    *(float2*)(out + (r + 8) * MDIM + c) = v1;
#pragma unroll
                    for (int v = 0; v < 4; v++) acc[i][j][v] = 0;
                }
            }
        }
    }
}

// ---------------------------------------------------------------------------
// Launch
// ---------------------------------------------------------------------------
extern "C" void kernel_launch(void* const* d_in, const int* in_sizes, int n_in,
                              void* d_out, int out_size) {
    const float* x = (const float*)d_in[0];  // [M,K]
    const float* y = (const float*)d_in[1];  // [K,N]
    float* out = (float*)d_out;

    static int nworkers = 0;
    if (nworkers == 0) {
        int dev = 0, sms = 148;
        cudaGetDevice(&dev);
        cudaDeviceGetAttribute(&sms, cudaDevAttrMultiProcessorCount, dev);
        nworkers = sms * 2;  // 2 CTAs/SM
        cudaFuncSetAttribute(gemm_kernel,
                             cudaFuncAttributeMaxDynamicSharedMemorySize,
                             SMEM_TOTAL);
    }

    convert_x_kernel<<<MDIM, 256>>>(x);
    transpose_y_kernel<<<dim3(MDIM / 64, MDIM / 64), 256>>>(y);
    colsum_kernel<<<MDIM, 256>>>();
    gemm_kernel<<<nworkers, 256, SMEM_TOTAL>>>(out, nworkers);
}

// round 8
// speedup vs baseline: 1.1523x; 1.0178x over previous
#include <cuda_runtime.h>
#include <cstdint>

// ============================================================================
// out[4096,4096] = ((x - xz)*sx) @ ((y - yz)*sy)
// Exact int8 GEMM (mma.sync m16n8k32 s8) + rank-1 zero-point correction.
// tcgen05 unavailable: harness lowers PTX to compute_103 (non-'a').
// R8: == R7 (BK=128 steps, ping-pong ldmatrix prefetch, fused colsum) with
//     the constant-term bug fixed: Cconst = S*K*xz*(yz-128)  (was 0).
// ============================================================================

#define MDIM 4096

static constexpr double X_SCALE = 0.03, X_ZP = -66.0;
static constexpr double Y_SCALE = 0.025, Y_ZP = 160.0;

// GEMM tiling
static constexpr int BM = 128, BN = 64, BK = 128, STAGES = 4;
static constexpr int ROWB = 144;                      // 128B data + 16B pad
static constexpr int A_STAGE = BM * ROWB;             // 18432
static constexpr int B_STAGE = BN * ROWB;             // 9216
static constexpr int STAGE_BYTES = A_STAGE + B_STAGE; // 27648
static constexpr int SMEM_TOTAL = STAGES * STAGE_BYTES; // 110592 (x2 CTAs/SM)
static constexpr int NT_N = MDIM / BN;                // 64
static constexpr int NTILES = (MDIM / BM) * NT_N;     // 2048
static constexpr int KITER = MDIM / BK;               // 32

// Scratch (device globals: allocation-free per harness rules)
__device__ char  g_x8 [(size_t)MDIM * MDIM];  // x as s8 (exact)
__device__ char  g_y8t[(size_t)MDIM * MDIM];  // (y-128)^T as s8, [N,K]
__device__ float g_rowsum[MDIM];              // sum_k x[m,k]        (exact int)
__device__ float g_colsum[MDIM];              // sum_k (y[k,n]-128)  (exact int)

// ---------------------------------------------------------------------------
// PTX helpers
// ---------------------------------------------------------------------------
__device__ __forceinline__ uint32_t smem_u32(const void* p) {
    uint32_t a;
    asm("{ .reg .u64 t; cvta.to.shared.u64 t, %1; cvt.u32.u64 %0, t; }"
        : "=r"(a) : "l"(p));
    return a;
}
__device__ __forceinline__ void cp_async16(uint32_t s, const void* g) {
    asm volatile("cp.async.cg.shared.global [%0], [%1], 16;" :: "r"(s), "l"(g));
}
#define CP_COMMIT() asm volatile("cp.async.commit_group;")
#define CP_WAIT2()  asm volatile("cp.async.wait_group 2;")

__device__ __forceinline__ void ldmatrix_x4(uint32_t* r, uint32_t addr) {
    asm volatile("ldmatrix.sync.aligned.m8n8.x4.shared.b16 {%0,%1,%2,%3}, [%4];"
                 : "=r"(r[0]), "=r"(r[1]), "=r"(r[2]), "=r"(r[3]) : "r"(addr));
}
__device__ __forceinline__ void mma_s8(int* d, const uint32_t* a, const uint32_t* b) {
    asm volatile(
        "mma.sync.aligned.m16n8k32.row.col.s32.s8.s8.s32 "
        "{%0,%1,%2,%3}, {%4,%5,%6,%7}, {%8,%9}, {%0,%1,%2,%3};"
        : "+r"(d[0]), "+r"(d[1]), "+r"(d[2]), "+r"(d[3])
        : "r"(a[0]), "r"(a[1]), "r"(a[2]), "r"(a[3]), "r"(b[0]), "r"(b[1]));
}

// ---------------------------------------------------------------------------
// Preprocessing
// ---------------------------------------------------------------------------
__global__ __launch_bounds__(256) void convert_x_kernel(const float* __restrict__ x) {
    int row = blockIdx.x;
    const float4* xr = (const float4*)(x + (size_t)row * MDIM);
    uchar4* xo = (uchar4*)(g_x8 + (size_t)row * MDIM);
    float s = 0.f;
#pragma unroll
    for (int q = 0; q < 4; q++) {
        int i = q * 256 + threadIdx.x;
        float4 v = xr[i];
        s += (v.x + v.y) + (v.z + v.w);
        uchar4 o;
        o.x = (unsigned char)(int)v.x;  // s8 bit pattern (exact)
        o.y = (unsigned char)(int)v.y;
        o.z = (unsigned char)(int)v.z;
        o.w = (unsigned char)(int)v.w;
        xo[i] = o;
    }
    __shared__ float red[256];
    red[threadIdx.x] = s;
    __syncthreads();
    for (int st = 128; st > 0; st >>= 1) {
        if (threadIdx.x < st) red[threadIdx.x] += red[threadIdx.x + st];
        __syncthreads();
    }
    if (threadIdx.x == 0) g_rowsum[row] = red[0];
}

// y8t[n][k] = (s8)(y[k][n] - 128); 64x64 tiles, 16B stores; fused colsum.
__global__ __launch_bounds__(256) void transpose_y_kernel(const float* __restrict__ y) {
    __shared__ float tile[64][65];
    int n0 = blockIdx.x * 64, k0 = blockIdx.y * 64;
    int tid = threadIdx.x;
    int col = tid & 63, r4 = tid >> 6;
#pragma unroll
    for (int p = 0; p < 16; p++) {
        int row = p * 4 + r4;
        tile[row][col] = y[(size_t)(k0 + row) * MDIM + n0 + col];
    }
    __syncthreads();
    int n = tid >> 2, kc = tid & 3;  // each thread: 16 k-values for column n
    uchar4 o[4];
    int part = 0;
#pragma unroll
    for (int q = 0; q < 4; q++) {
        int k = kc * 16 + q * 4;
        int v0 = (int)tile[k + 0][n] - 128, v1 = (int)tile[k + 1][n] - 128;
        int v2 = (int)tile[k + 2][n] - 128, v3 = (int)tile[k + 3][n] - 128;
        part += v0 + v1 + v2 + v3;
        o[q].x = (unsigned char)v0; o[q].y = (unsigned char)v1;
        o[q].z = (unsigned char)v2; o[q].w = (unsigned char)v3;
    }
    *(uint4*)(g_y8t + (size_t)(n0 + n) * MDIM + k0 + kc * 16) = *(uint4*)o;
    atomicAdd(&g_colsum[n0 + n], (float)part);  // exact ints: order-independent
}

// ---------------------------------------------------------------------------
// GEMM: persistent workers, CTA tile 128x64, 256 thr (8 warps, warp 32x32),
// BK=128 per pipeline step, 4 stages, ping-pong ldmatrix prefetch.
// ---------------------------------------------------------------------------
__global__ __launch_bounds__(256, 2) void gemm_kernel(float* __restrict__ out,
                                                      int nworkers) {
    extern __shared__ __align__(128) char smem[];
    const uint32_t sbase = smem_u32(smem);
    const int tid = threadIdx.x, lane = tid & 31, wid = tid >> 5;
    const int worker = blockIdx.x;
    const int wm = (wid >> 1) * 32;   // warp m-offset 0..96
    const int wn = (wid & 1) * 32;    // warp n-offset 0/32

    const int cnt = (worker < NTILES) ? (NTILES - 1 - worker) / nworkers + 1 : 0;
    const int total = cnt * KITER;
    if (total == 0) return;

    // loader mapping: 16B chunks, rows of 128B data at stride ROWB
    const int lrow = tid >> 3, lch = (tid & 7) * 16;  // 32 rows x 8 chunks / pass

    auto load_g = [&](int g) {
        int t = worker + (g >> 5) * nworkers;   // tile id
        int kt = g & (KITER - 1);
        const char* gA = g_x8  + (size_t)((t >> 6) * BM) * MDIM + kt * BK;
        const char* gB = g_y8t + (size_t)((t & (NT_N - 1)) * BN) * MDIM + kt * BK;
        uint32_t sA = sbase + (g & 3) * STAGE_BYTES;
        uint32_t sB = sA + A_STAGE;
#pragma unroll
        for (int q = 0; q < 4; q++) {  // A: 128 rows
            int row = lrow + q * 32;
            cp_async16(sA + row * ROWB + lch, gA + (size_t)row * MDIM + lch);
        }
#pragma unroll
        for (int q = 0; q < 2; q++) {  // B: 64 rows
            int row = lrow + q * 32;
            cp_async16(sB + row * ROWB + lch, gB + (size_t)row * MDIM + lch);
        }
    };

    // ldmatrix lane addressing (fragment layout identical to R5/R6 passing code)
    const int rA = (lane & 7) + ((lane >> 3) & 1) * 8;  // 0..15
    const int cA = (lane >> 4) * 16;                    // 0/16
    const int rB = (lane & 7) + (lane >> 4) * 8;        // j-pair packing
    const int cB = ((lane >> 3) & 1) * 16;

    int acc[2][4][4];
#pragma unroll
    for (int i = 0; i < 2; i++)
#pragma unroll
        for (int j = 0; j < 4; j++)
#pragma unroll
            for (int v = 0; v < 4; v++) acc[i][j][v] = 0;

    // Epilogue constants.
    // out = S*P + S*(128-yz)*rowsum_x[m] - S*xz*colsum_shift[n]
    //       + S*K*xz*(yz-128)
    // where colsum_shift = sum_k (y[k,n]-128)  (what transpose accumulates).
    constexpr double Sd = X_SCALE * Y_SCALE;
    const float Sc     = (float)Sd;
    const float Crow   = (float)(Sd * (128.0 - Y_ZP));
    const float Ccol   = (float)(-Sd * X_ZP);
    const float Cconst = (float)(Sd * (double)MDIM * X_ZP * (Y_ZP - 128.0));

    const int rr = lane >> 2, cc = (lane & 3) * 2;

#pragma unroll
    for (int g = 0; g < STAGES - 1; g++) { load_g(g); CP_COMMIT(); }

    uint32_t a[2][2][4], b[2][2][4];  // ping-pong fragments

#pragma unroll 1
    for (int g = 0; g < total; ++g) {
        CP_WAIT2();
        __syncthreads();
        if (g + 3 < total) load_g(g + 3);
        CP_COMMIT();  // exactly one group per iteration

        const uint32_t aW = sbase + (g & 3) * STAGE_BYTES + (wm + rA) * ROWB + cA;
        const uint32_t bW = sbase + (g & 3) * STAGE_BYTES + A_STAGE +
                            (wn + rB) * ROWB + cB;

        ldmatrix_x4(a[0][0], aW);
        ldmatrix_x4(a[0][1], aW + 16 * ROWB);
        ldmatrix_x4(b[0][0], bW);
        ldmatrix_x4(b[0][1], bW + 16 * ROWB);
#pragma unroll
        for (int ks = 0; ks < 4; ks++) {
            const int pp = ks & 1;
            if (ks < 3) {  // prefetch next k-chunk while MMAs of this one issue
                const int np = pp ^ 1, off = (ks + 1) * 32;
                ldmatrix_x4(a[np][0], aW + off);
                ldmatrix_x4(a[np][1], aW + 16 * ROWB + off);
                ldmatrix_x4(b[np][0], bW + off);
                ldmatrix_x4(b[np][1], bW + 16 * ROWB + off);
            }
            mma_s8(acc[0][0], a[pp][0], b[pp][0] + 0);
            mma_s8(acc[0][1], a[pp][0], b[pp][0] + 2);
            mma_s8(acc[0][2], a[pp][0], b[pp][1] + 0);
            mma_s8(acc[0][3], a[pp][0], b[pp][1] + 2);
            mma_s8(acc[1][0], a[pp][1], b[pp][0] + 0);
            mma_s8(acc[1][1], a[pp][1], b[pp][0] + 2);
            mma_s8(acc[1][2], a[pp][1], b[pp][1] + 0);
            mma_s8(acc[1][3], a[pp][1], b[pp][1] + 2);
        }

        if ((g & (KITER - 1)) == KITER - 1) {
            // Register-only epilogue (no smem, no sync)
            int t = worker + (g >> 5) * nworkers;
            int m0 = (t >> 6) * BM, n0 = (t & (NT_N - 1)) * BN;
            float rowC[2][2], colC[4][2];
#pragma unroll
            for (int i = 0; i < 2; i++) {
                int r = m0 + wm + i * 16 + rr;
                rowC[i][0] = Crow * g_rowsum[r]     + Cconst;
                rowC[i][1] = Crow * g_rowsum[r + 8] + Cconst;
            }
#pragma unroll
            for (int j = 0; j < 4; j++) {
                int c = n0 + wn + j * 8 + cc;
                colC[j][0] = Ccol * g_colsum[c];
                colC[j][1] = Ccol * g_colsum[c + 1];
            }
#pragma unroll
            for (int i = 0; i < 2; i++) {
#pragma unroll
                for (int j = 0; j < 4; j++) {
                    size_t r = (size_t)(m0 + wm + i * 16 + rr);
                    size_t c = (size_t)(n0 + wn + j * 8 + cc);
                    float2 v0, v1;
                    v0.x = Sc * (float)acc[i][j][0] + rowC[i][0] + colC[j][0];
                    v0.y = Sc * (float)acc[i][j][1] + rowC[i][0] + colC[j][1];
                    v1.x = Sc * (float)acc[i][j][2] + rowC[i][1] + colC[j][0];
                    v1.y = Sc * (float)acc[i][j][3] + rowC[i][1] + colC[j][1];
                    *(float2*)(out + r * MDIM + c)       = v0;
                    *(float2*)(out + (r + 8) * MDIM + c) = v1;
#pragma unroll
                    for (int v = 0; v < 4; v++) acc[i][j][v] = 0;
                }
            }
        }
    }
}

// ---------------------------------------------------------------------------
// Launch
// ---------------------------------------------------------------------------
extern "C" void kernel_launch(void* const* d_in, const int* in_sizes, int n_in,
                              void* d_out, int out_size) {
    const float* x = (const float*)d_in[0];  // [M,K]
    const float* y = (const float*)d_in[1];  // [K,N]
    float* out = (float*)d_out;

    static int nworkers = 0;
    if (nworkers == 0) {
        int dev = 0, sms = 148;
        cudaGetDevice(&dev);
        cudaDeviceGetAttribute(&sms, cudaDevAttrMultiProcessorCount, dev);
        nworkers = sms * 2;  // 2 CTAs/SM
        cudaFuncSetAttribute(gemm_kernel,
                             cudaFuncAttributeMaxDynamicSharedMemorySize,
                             SMEM_TOTAL);
    }

    void* csym = nullptr;
    cudaGetSymbolAddress(&csym, g_colsum);
    cudaMemsetAsync(csym, 0, MDIM * sizeof(float), 0);  // atomics need re-zero

    convert_x_kernel<<<MDIM, 256>>>(x);
    transpose_y_kernel<<<dim3(MDIM / 64, MDIM / 64), 256>>>(y);
    gemm_kernel<<<nworkers, 256, SMEM_TOTAL>>>(out, nworkers);
}

// round 11
// speedup vs baseline: 1.2765x; 1.1078x over previous
#include <cuda_runtime.h>
#include <cstdint>

// ============================================================================
// out[4096,4096] = ((x - xz)*sx) @ ((y - yz)*sy)
// Exact int8 GEMM + rank-1 zero-point correction.
// tcgen05 unavailable (harness lowers PTX to compute_103, non-'a').
// R9: HYBRID — legacy-tensor mma.sync (cols 0..95, 12 warps) + dp4a on the
//     integer pipe (cols 96..127, 4 warps) sharing one smem pipeline.
//     Tensor pipe was 87.7% busy and is the binding resource; dp4a adds
//     ~33% more columns per step on an otherwise-idle pipe.
// ============================================================================

#define MDIM 4096

static constexpr double X_SCALE = 0.03, X_ZP = -66.0;
static constexpr double Y_SCALE = 0.025, Y_ZP = 160.0;

// GEMM tiling
static constexpr int BM = 128, BN = 128, BK = 128, STAGES = 4;
static constexpr int BN_T = 96;                       // tensor columns
static constexpr int ROWB = 144;                      // 128B data + 16B pad
static constexpr int A_STAGE = BM * ROWB;             // 18432
static constexpr int B_STAGE = BN * ROWB;             // 18432
static constexpr int STAGE_BYTES = A_STAGE + B_STAGE; // 36864
static constexpr int SMEM_TOTAL = STAGES * STAGE_BYTES; // 147456 (1 CTA/SM)
static constexpr int NT_N = MDIM / BN;                // 32
static constexpr int NTILES = (MDIM / BM) * NT_N;     // 1024
static constexpr int KITER = MDIM / BK;               // 32

// Scratch (device globals: allocation-free per harness rules)
__device__ char  g_x8 [(size_t)MDIM * MDIM];  // x as s8 (exact)
__device__ char  g_y8t[(size_t)MDIM * MDIM];  // (y-128)^T as s8, [N,K]
__device__ float g_rowsum[MDIM];              // sum_k x[m,k]        (exact int)
__device__ float g_colsum[MDIM];              // sum_k (y[k,n]-128)  (exact int)

// ---------------------------------------------------------------------------
// PTX helpers
// ---------------------------------------------------------------------------
__device__ __forceinline__ uint32_t smem_u32(const void* p) {
    uint32_t a;
    asm("{ .reg .u64 t; cvta.to.shared.u64 t, %1; cvt.u32.u64 %0, t; }"
        : "=r"(a) : "l"(p));
    return a;
}
__device__ __forceinline__ void cp_async16(uint32_t s, const void* g) {
    asm volatile("cp.async.cg.shared.global [%0], [%1], 16;" :: "r"(s), "l"(g));
}
#define CP_COMMIT() asm volatile("cp.async.commit_group;")
#define CP_WAIT2()  asm volatile("cp.async.wait_group 2;")

__device__ __forceinline__ void ldmatrix_x4(uint32_t* r, uint32_t addr) {
    asm volatile("ldmatrix.sync.aligned.m8n8.x4.shared.b16 {%0,%1,%2,%3}, [%4];"
                 : "=r"(r[0]), "=r"(r[1]), "=r"(r[2]), "=r"(r[3]) : "r"(addr));
}
__device__ __forceinline__ void mma_s8(int* d, const uint32_t* a, const uint32_t* b) {
    asm volatile(
        "mma.sync.aligned.m16n8k32.row.col.s32.s8.s8.s32 "
        "{%0,%1,%2,%3}, {%4,%5,%6,%7}, {%8,%9}, {%0,%1,%2,%3};"
        : "+r"(d[0]), "+r"(d[1]), "+r"(d[2]), "+r"(d[3])
        : "r"(a[0]), "r"(a[1]), "r"(a[2]), "r"(a[3]), "r"(b[0]), "r"(b[1]));
}

// ---------------------------------------------------------------------------
// Preprocessing (unchanged from R8-passing)
// ---------------------------------------------------------------------------
__global__ __launch_bounds__(256) void convert_x_kernel(const float* __restrict__ x) {
    int row = blockIdx.x;
    const float4* xr = (const float4*)(x + (size_t)row * MDIM);
    uchar4* xo = (uchar4*)(g_x8 + (size_t)row * MDIM);
    float s = 0.f;
#pragma unroll
    for (int q = 0; q < 4; q++) {
        int i = q * 256 + threadIdx.x;
        float4 v = xr[i];
        s += (v.x + v.y) + (v.z + v.w);
        uchar4 o;
        o.x = (unsigned char)(int)v.x;
        o.y = (unsigned char)(int)v.y;
        o.z = (unsigned char)(int)v.z;
        o.w = (unsigned char)(int)v.w;
        xo[i] = o;
    }
    __shared__ float red[256];
    red[threadIdx.x] = s;
    __syncthreads();
    for (int st = 128; st > 0; st >>= 1) {
        if (threadIdx.x < st) red[threadIdx.x] += red[threadIdx.x + st];
        __syncthreads();
    }
    if (threadIdx.x == 0) g_rowsum[row] = red[0];
}

__global__ __launch_bounds__(256) void transpose_y_kernel(const float* __restrict__ y) {
    __shared__ float tile[64][65];
    int n0 = blockIdx.x * 64, k0 = blockIdx.y * 64;
    int tid = threadIdx.x;
    int col = tid & 63, r4 = tid >> 6;
#pragma unroll
    for (int p = 0; p < 16; p++) {
        int row = p * 4 + r4;
        tile[row][col] = y[(size_t)(k0 + row) * MDIM + n0 + col];
    }
    __syncthreads();
    int n = tid >> 2, kc = tid & 3;
    uchar4 o[4];
    int part = 0;
#pragma unroll
    for (int q = 0; q < 4; q++) {
        int k = kc * 16 + q * 4;
        int v0 = (int)tile[k + 0][n] - 128, v1 = (int)tile[k + 1][n] - 128;
        int v2 = (int)tile[k + 2][n] - 128, v3 = (int)tile[k + 3][n] - 128;
        part += v0 + v1 + v2 + v3;
        o[q].x = (unsigned char)v0; o[q].y = (unsigned char)v1;
        o[q].z = (unsigned char)v2; o[q].w = (unsigned char)v3;
    }
    *(uint4*)(g_y8t + (size_t)(n0 + n) * MDIM + k0 + kc * 16) = *(uint4*)o;
    atomicAdd(&g_colsum[n0 + n], (float)part);
}

// ---------------------------------------------------------------------------
// Hybrid GEMM: persistent workers, CTA tile 128x128, 512 thr / 16 warps:
//   warps 0..11 : mma.sync, warp tile 32x32, cols [0,96)
//   warps 12..15: dp4a,     warp tile 32x32, cols [96,128)
// BK=128 per step, 4 stages, one cp.async group per step.
// ---------------------------------------------------------------------------
__global__ __launch_bounds__(512, 1) void gemm_kernel(float* __restrict__ out,
                                                      int nworkers) {
    extern __shared__ __align__(128) char smem[];
    const uint32_t sbase = smem_u32(smem);
    const int tid = threadIdx.x, lane = tid & 31, wid = tid >> 5;
    const int worker = blockIdx.x;

    const int cnt = (worker < NTILES) ? (NTILES - 1 - worker) / nworkers + 1 : 0;
    const int total = cnt * KITER;
    if (total == 0) return;

    // loader mapping: 256 rows x 8 x 16B = 2048 chunks, 4 per thread
    const int lrow = tid >> 3, lch = (tid & 7) * 16;  // 64 rows per pass

    auto load_g = [&](int g) {
        int t = worker + (g >> 5) * nworkers;
        int kt = g & (KITER - 1);
        const char* gA = g_x8  + (size_t)((t >> 5) * BM) * MDIM + kt * BK;
        const char* gB = g_y8t + (size_t)((t & (NT_N - 1)) * BN) * MDIM + kt * BK;
        uint32_t sA = sbase + (g & 3) * STAGE_BYTES;
        uint32_t sB = sA + A_STAGE;
#pragma unroll
        for (int q = 0; q < 2; q++) {  // A: 128 rows
            int row = lrow + q * 64;
            cp_async16(sA + row * ROWB + lch, gA + (size_t)row * MDIM + lch);
        }
#pragma unroll
        for (int q = 0; q < 2; q++) {  // B: 128 rows
            int row = lrow + q * 64;
            cp_async16(sB + row * ROWB + lch, gB + (size_t)row * MDIM + lch);
        }
    };

    // ---- role-specific state ----
    // Tensor warps (0..11): wm in {0,32,64,96}, wn in {0,32,64}
    const int wm = (wid < 12) ? (wid / 3) * 32 : 0;
    const int wn = (wid < 12) ? (wid % 3) * 32 : 0;
    const int rA = (lane & 7) + ((lane >> 3) & 1) * 8;
    const int cA = (lane >> 4) * 16;
    const int rB = (lane & 7) + (lane >> 4) * 8;
    const int cB = ((lane >> 3) & 1) * 16;

    // dp4a warps (12..15): row block = dwid*32, cols 96..127
    const int dwid = wid - 12;
    const int rg = lane >> 2;        // 0..7 ; thread rows rg + 8i
    const int cg = lane & 3;         // 0..3 ; thread cols cg + 4j

    int acc[2][4][4];                // tensor accumulators
    int dacc[4][8];                  // dp4a accumulators (4 rows x 8 cols)
#pragma unroll
    for (int i = 0; i < 2; i++)
#pragma unroll
        for (int j = 0; j < 4; j++)
#pragma unroll
            for (int v = 0; v < 4; v++) acc[i][j][v] = 0;
#pragma unroll
    for (int i = 0; i < 4; i++)
#pragma unroll
        for (int j = 0; j < 8; j++) dacc[i][j] = 0;

    // Epilogue constants:
    // out = S*P + S*(128-yz)*rowsum_x[m] - S*xz*colsum_shift[n] + S*K*xz*(yz-128)
    constexpr double Sd = X_SCALE * Y_SCALE;
    const float Sc     = (float)Sd;
    const float Crow   = (float)(Sd * (128.0 - Y_ZP));
    const float Ccol   = (float)(-Sd * X_ZP);
    const float Cconst = (float)(Sd * (double)MDIM * X_ZP * (Y_ZP - 128.0));
    const int rr = lane >> 2, cc = (lane & 3) * 2;

#pragma unroll
    for (int g = 0; g < STAGES - 1; g++) { load_g(g); CP_COMMIT(); }

    uint32_t a[2][2][4], b[2][2][4];  // tensor ping-pong fragments

#pragma unroll 1
    for (int g = 0; g < total; ++g) {
        CP_WAIT2();
        __syncthreads();
        if (g + 3 < total) load_g(g + 3);
        CP_COMMIT();

        const uint32_t stg = sbase + (g & 3) * STAGE_BYTES;
        const bool last_k = (g & (KITER - 1)) == KITER - 1;
        int t = worker + (g >> 5) * nworkers;
        int m0 = (t >> 5) * BM, n0 = (t & (NT_N - 1)) * BN;

        if (wid < 12) {
            // ---------------- tensor path: 32x32 x k128 ----------------
            const uint32_t aW = stg + (wm + rA) * ROWB + cA;
            const uint32_t bW = stg + A_STAGE + (wn + rB) * ROWB + cB;

            ldmatrix_x4(a[0][0], aW);
            ldmatrix_x4(a[0][1], aW + 16 * ROWB);
            ldmatrix_x4(b[0][0], bW);
            ldmatrix_x4(b[0][1], bW + 16 * ROWB);
#pragma unroll
            for (int ks = 0; ks < 4; ks++) {
                const int pp = ks & 1;
                if (ks < 3) {
                    const int np = pp ^ 1, off = (ks + 1) * 32;
                    ldmatrix_x4(a[np][0], aW + off);
                    ldmatrix_x4(a[np][1], aW + 16 * ROWB + off);
                    ldmatrix_x4(b[np][0], bW + off);
                    ldmatrix_x4(b[np][1], bW + 16 * ROWB + off);
                }
                mma_s8(acc[0][0], a[pp][0], b[pp][0] + 0);
                mma_s8(acc[0][1], a[pp][0], b[pp][0] + 2);
                mma_s8(acc[0][2], a[pp][0], b[pp][1] + 0);
                mma_s8(acc[0][3], a[pp][0], b[pp][1] + 2);
                mma_s8(acc[1][0], a[pp][1], b[pp][0] + 0);
                mma_s8(acc[1][1], a[pp][1], b[pp][0] + 2);
                mma_s8(acc[1][2], a[pp][1], b[pp][1] + 0);
                mma_s8(acc[1][3], a[pp][1], b[pp][1] + 2);
            }

            if (last_k) {
                float rowC[2][2], colC[4][2];
#pragma unroll
                for (int i = 0; i < 2; i++) {
                    int r = m0 + wm + i * 16 + rr;
                    rowC[i][0] = Crow * g_rowsum[r]     + Cconst;
                    rowC[i][1] = Crow * g_rowsum[r + 8] + Cconst;
                }
#pragma unroll
                for (int j = 0; j < 4; j++) {
                    int c = n0 + wn + j * 8 + cc;
                    colC[j][0] = Ccol * g_colsum[c];
                    colC[j][1] = Ccol * g_colsum[c + 1];
                }
#pragma unroll
                for (int i = 0; i < 2; i++) {
#pragma unroll
                    for (int j = 0; j < 4; j++) {
                        size_t r = (size_t)(m0 + wm + i * 16 + rr);
                        size_t c = (size_t)(n0 + wn + j * 8 + cc);
                        float2 v0, v1;
                        v0.x = Sc * (float)acc[i][j][0] + rowC[i][0] + colC[j][0];
                        v0.y = Sc * (float)acc[i][j][1] + rowC[i][0] + colC[j][1];
                        v1.x = Sc * (float)acc[i][j][2] + rowC[i][1] + colC[j][0];
                        v1.y = Sc * (float)acc[i][j][3] + rowC[i][1] + colC[j][1];
                        *(float2*)(out + r * MDIM + c)       = v0;
                        *(float2*)(out + (r + 8) * MDIM + c) = v1;
#pragma unroll
                        for (int v = 0; v < 4; v++) acc[i][j][v] = 0;
                    }
                }
            }
        } else {
            // ---------------- dp4a path: 32 rows x 32 cols x k128 ------
            const char* sA = smem + (g & 3) * STAGE_BYTES;
            const char* sB = sA + A_STAGE + BN_T * ROWB;  // cols 96..127
            const int rbase = dwid * 32 + rg;
#pragma unroll 2
            for (int kk = 0; kk < 8; kk++) {
                int4 av[4], bv[8];
#pragma unroll
                for (int i = 0; i < 4; i++)
                    av[i] = *(const int4*)(sA + (rbase + 8 * i) * ROWB + kk * 16);
#pragma unroll
                for (int j = 0; j < 8; j++)
                    bv[j] = *(const int4*)(sB + (cg + 4 * j) * ROWB + kk * 16);
#pragma unroll
                for (int i = 0; i < 4; i++)
#pragma unroll
                    for (int j = 0; j < 8; j++) {
                        int s = dacc[i][j];
                        s = __dp4a(av[i].x, bv[j].x, s);
                        s = __dp4a(av[i].y, bv[j].y, s);
                        s = __dp4a(av[i].z, bv[j].z, s);
                        s = __dp4a(av[i].w, bv[j].w, s);
                        dacc[i][j] = s;
                    }
            }

            if (last_k) {
#pragma unroll
                for (int i = 0; i < 4; i++) {
                    int r = m0 + dwid * 32 + rg + 8 * i;
                    float rc = Crow * g_rowsum[r] + Cconst;
#pragma unroll
                    for (int j = 0; j < 8; j++) {
                        int c = n0 + BN_T + cg + 4 * j;
                        out[(size_t)r * MDIM + c] =
                            Sc * (float)dacc[i][j] + rc + Ccol * g_colsum[c];
                        dacc[i][j] = 0;
                    }
                }
            }
        }
    }
}

// ---------------------------------------------------------------------------
// Launch
// ---------------------------------------------------------------------------
extern "C" void kernel_launch(void* const* d_in, const int* in_sizes, int n_in,
                              void* d_out, int out_size) {
    const float* x = (const float*)d_in[0];  // [M,K]
    const float* y = (const float*)d_in[1];  // [K,N]
    float* out = (float*)d_out;

    static int nworkers = 0;
    if (nworkers == 0) {
        int dev = 0, sms = 148;
        cudaGetDevice(&dev);
        cudaDeviceGetAttribute(&sms, cudaDevAttrMultiProcessorCount, dev);
        nworkers = sms;  // 1 CTA/SM (smem 144KB)
        cudaFuncSetAttribute(gemm_kernel,
                             cudaFuncAttributeMaxDynamicSharedMemorySize,
                             SMEM_TOTAL);
    }

    void* csym = nullptr;
    cudaGetSymbolAddress(&csym, g_colsum);
    cudaMemsetAsync(csym, 0, MDIM * sizeof(float), 0);

    convert_x_kernel<<<MDIM, 256>>>(x);
    transpose_y_kernel<<<dim3(MDIM / 64, MDIM / 64), 256>>>(y);
    gemm_kernel<<<nworkers, 512, SMEM_TOTAL>>>(out, nworkers);
}

// round 15
// speedup vs baseline: 1.6067x; 1.2587x over previous
#include <cuda_runtime.h>
#include <cstdint>

// ============================================================================
// out[4096,4096] = ((x - xz)*sx) @ ((y - yz)*sy)
// Exact int8 GEMM + rank-1 zero-point correction.
// tcgen05 unavailable (harness lowers PTX to compute_103, non-'a').
// R12: rebalanced hybrid — tensor mma.sync cols [0,64) (8 warps) and dp4a
//      cols [64,128) (8 warps). Per-SMSP: 2 tensor + 2 dp4a warps; both
//      engines ~64 MACs/cyc/SMSP -> balanced at ~4100 cyc/step vs 7000.
// ============================================================================

#define MDIM 4096

static constexpr double X_SCALE = 0.03, X_ZP = -66.0;
static constexpr double Y_SCALE = 0.025, Y_ZP = 160.0;

// GEMM tiling
static constexpr int BM = 128, BN = 128, BK = 128, STAGES = 4;
static constexpr int BN_T = 64;                       // tensor columns
static constexpr int ROWB = 144;                      // 128B data + 16B pad
static constexpr int A_STAGE = BM * ROWB;             // 18432
static constexpr int B_STAGE = BN * ROWB;             // 18432
static constexpr int STAGE_BYTES = A_STAGE + B_STAGE; // 36864
static constexpr int SMEM_TOTAL = STAGES * STAGE_BYTES; // 147456 (1 CTA/SM)
static constexpr int NT_N = MDIM / BN;                // 32
static constexpr int NTILES = (MDIM / BM) * NT_N;     // 1024
static constexpr int KITER = MDIM / BK;               // 32

// Scratch (device globals: allocation-free per harness rules)
__device__ char  g_x8 [(size_t)MDIM * MDIM];  // x as s8 (exact)
__device__ char  g_y8t[(size_t)MDIM * MDIM];  // (y-128)^T as s8, [N,K]
__device__ float g_rowsum[MDIM];              // sum_k x[m,k]        (exact int)
__device__ float g_colsum[MDIM];              // sum_k (y[k,n]-128)  (exact int)

// ---------------------------------------------------------------------------
// PTX helpers
// ---------------------------------------------------------------------------
__device__ __forceinline__ uint32_t smem_u32(const void* p) {
    uint32_t a;
    asm("{ .reg .u64 t; cvta.to.shared.u64 t, %1; cvt.u32.u64 %0, t; }"
        : "=r"(a) : "l"(p));
    return a;
}
__device__ __forceinline__ void cp_async16(uint32_t s, const void* g) {
    asm volatile("cp.async.cg.shared.global [%0], [%1], 16;" :: "r"(s), "l"(g));
}
#define CP_COMMIT() asm volatile("cp.async.commit_group;")
#define CP_WAIT2()  asm volatile("cp.async.wait_group 2;")

__device__ __forceinline__ void ldmatrix_x4(uint32_t* r, uint32_t addr) {
    asm volatile("ldmatrix.sync.aligned.m8n8.x4.shared.b16 {%0,%1,%2,%3}, [%4];"
                 : "=r"(r[0]), "=r"(r[1]), "=r"(r[2]), "=r"(r[3]) : "r"(addr));
}
__device__ __forceinline__ void mma_s8(int* d, const uint32_t* a, const uint32_t* b) {
    asm volatile(
        "mma.sync.aligned.m16n8k32.row.col.s32.s8.s8.s32 "
        "{%0,%1,%2,%3}, {%4,%5,%6,%7}, {%8,%9}, {%0,%1,%2,%3};"
        : "+r"(d[0]), "+r"(d[1]), "+r"(d[2]), "+r"(d[3])
        : "r"(a[0]), "r"(a[1]), "r"(a[2]), "r"(a[3]), "r"(b[0]), "r"(b[1]));
}

// ---------------------------------------------------------------------------
// Preprocessing (unchanged from R8/R11-passing)
// ---------------------------------------------------------------------------
__global__ __launch_bounds__(256) void convert_x_kernel(const float* __restrict__ x) {
    int row = blockIdx.x;
    const float4* xr = (const float4*)(x + (size_t)row * MDIM);
    uchar4* xo = (uchar4*)(g_x8 + (size_t)row * MDIM);
    float s = 0.f;
#pragma unroll
    for (int q = 0; q < 4; q++) {
        int i = q * 256 + threadIdx.x;
        float4 v = xr[i];
        s += (v.x + v.y) + (v.z + v.w);
        uchar4 o;
        o.x = (unsigned char)(int)v.x;
        o.y = (unsigned char)(int)v.y;
        o.z = (unsigned char)(int)v.z;
        o.w = (unsigned char)(int)v.w;
        xo[i] = o;
    }
    __shared__ float red[256];
    red[threadIdx.x] = s;
    __syncthreads();
    for (int st = 128; st > 0; st >>= 1) {
        if (threadIdx.x < st) red[threadIdx.x] += red[threadIdx.x + st];
        __syncthreads();
    }
    if (threadIdx.x == 0) g_rowsum[row] = red[0];
}

__global__ __launch_bounds__(256) void transpose_y_kernel(const float* __restrict__ y) {
    __shared__ float tile[64][65];
    int n0 = blockIdx.x * 64, k0 = blockIdx.y * 64;
    int tid = threadIdx.x;
    int col = tid & 63, r4 = tid >> 6;
#pragma unroll
    for (int p = 0; p < 16; p++) {
        int row = p * 4 + r4;
        tile[row][col] = y[(size_t)(k0 + row) * MDIM + n0 + col];
    }
    __syncthreads();
    int n = tid >> 2, kc = tid & 3;
    uchar4 o[4];
    int part = 0;
#pragma unroll
    for (int q = 0; q < 4; q++) {
        int k = kc * 16 + q * 4;
        int v0 = (int)tile[k + 0][n] - 128, v1 = (int)tile[k + 1][n] - 128;
        int v2 = (int)tile[k + 2][n] - 128, v3 = (int)tile[k + 3][n] - 128;
        part += v0 + v1 + v2 + v3;
        o[q].x = (unsigned char)v0; o[q].y = (unsigned char)v1;
        o[q].z = (unsigned char)v2; o[q].w = (unsigned char)v3;
    }
    *(uint4*)(g_y8t + (size_t)(n0 + n) * MDIM + k0 + kc * 16) = *(uint4*)o;
    atomicAdd(&g_colsum[n0 + n], (float)part);
}

// ---------------------------------------------------------------------------
// Hybrid GEMM: persistent workers, CTA tile 128x128, 512 thr / 16 warps:
//   warps 0..7  : mma.sync, warp tile 32x32, cols [0,64)   (2 per SMSP)
//   warps 8..15 : dp4a,     warp tile 32x32, cols [64,128) (2 per SMSP)
// BK=128 per step, 4 stages, one cp.async group per step.
// ---------------------------------------------------------------------------
__global__ __launch_bounds__(512, 1) void gemm_kernel(float* __restrict__ out,
                                                      int nworkers) {
    extern __shared__ __align__(128) char smem[];
    const uint32_t sbase = smem_u32(smem);
    const int tid = threadIdx.x, lane = tid & 31, wid = tid >> 5;
    const int worker = blockIdx.x;

    const int cnt = (worker < NTILES) ? (NTILES - 1 - worker) / nworkers + 1 : 0;
    const int total = cnt * KITER;
    if (total == 0) return;

    // loader mapping: 256 rows x 8 x 16B = 2048 chunks, 4 per thread
    const int lrow = tid >> 3, lch = (tid & 7) * 16;  // 64 rows per pass

    auto load_g = [&](int g) {
        int t = worker + (g >> 5) * nworkers;
        int kt = g & (KITER - 1);
        const char* gA = g_x8  + (size_t)((t >> 5) * BM) * MDIM + kt * BK;
        const char* gB = g_y8t + (size_t)((t & (NT_N - 1)) * BN) * MDIM + kt * BK;
        uint32_t sA = sbase + (g & 3) * STAGE_BYTES;
        uint32_t sB = sA + A_STAGE;
#pragma unroll
        for (int q = 0; q < 2; q++) {  // A: 128 rows
            int row = lrow + q * 64;
            cp_async16(sA + row * ROWB + lch, gA + (size_t)row * MDIM + lch);
        }
#pragma unroll
        for (int q = 0; q < 2; q++) {  // B: 128 rows
            int row = lrow + q * 64;
            cp_async16(sB + row * ROWB + lch, gB + (size_t)row * MDIM + lch);
        }
    };

    // ---- role split: wid 0..7 tensor, wid 8..15 dp4a (2 of each per SMSP) --
    const bool is_tensor = (wid < 8);

    // Tensor warps: 4m x 2n of 32x32 tiles over cols [0,64)
    const int wm = (wid >> 1) * 32;
    const int wn = (wid & 1) * 32;
    const int rA = (lane & 7) + ((lane >> 3) & 1) * 8;
    const int cA = (lane >> 4) * 16;
    const int rB = (lane & 7) + (lane >> 4) * 8;
    const int cB = ((lane >> 3) & 1) * 16;

    // dp4a warps: dwid 0..7 -> rows (dwid&3)*32, col block 64+(dwid>>2)*32
    const int dwid = wid - 8;
    const int colblk = (dwid >> 2) * 32;          // 0 or 32 within dp4a half
    const int rg = lane >> 2;                     // 0..7 ; rows rg + 8i
    const int cg = lane & 3;                      // 0..3 ; cols cg + 4j

    int acc[2][4][4];                // tensor accumulators
    int dacc[4][8];                  // dp4a accumulators (4 rows x 8 cols)
#pragma unroll
    for (int i = 0; i < 2; i++)
#pragma unroll
        for (int j = 0; j < 4; j++)
#pragma unroll
            for (int v = 0; v < 4; v++) acc[i][j][v] = 0;
#pragma unroll
    for (int i = 0; i < 4; i++)
#pragma unroll
        for (int j = 0; j < 8; j++) dacc[i][j] = 0;

    // Epilogue constants:
    // out = S*P + S*(128-yz)*rowsum_x[m] - S*xz*colsum_shift[n] + S*K*xz*(yz-128)
    constexpr double Sd = X_SCALE * Y_SCALE;
    const float Sc     = (float)Sd;
    const float Crow   = (float)(Sd * (128.0 - Y_ZP));
    const float Ccol   = (float)(-Sd * X_ZP);
    const float Cconst = (float)(Sd * (double)MDIM * X_ZP * (Y_ZP - 128.0));
    const int rr = lane >> 2, cc = (lane & 3) * 2;

#pragma unroll
    for (int g = 0; g < STAGES - 1; g++) { load_g(g); CP_COMMIT(); }

    uint32_t a[2][2][4], b[2][2][4];  // tensor ping-pong fragments

#pragma unroll 1
    for (int g = 0; g < total; ++g) {
        CP_WAIT2();
        __syncthreads();
        if (g + 3 < total) load_g(g + 3);
        CP_COMMIT();

        const uint32_t stg = sbase + (g & 3) * STAGE_BYTES;
        const bool last_k = (g & (KITER - 1)) == KITER - 1;
        int t = worker + (g >> 5) * nworkers;
        int m0 = (t >> 5) * BM, n0 = (t & (NT_N - 1)) * BN;

        if (is_tensor) {
            // ---------------- tensor path: 32x32 x k128 ----------------
            const uint32_t aW = stg + (wm + rA) * ROWB + cA;
            const uint32_t bW = stg + A_STAGE + (wn + rB) * ROWB + cB;

            ldmatrix_x4(a[0][0], aW);
            ldmatrix_x4(a[0][1], aW + 16 * ROWB);
            ldmatrix_x4(b[0][0], bW);
            ldmatrix_x4(b[0][1], bW + 16 * ROWB);
#pragma unroll
            for (int ks = 0; ks < 4; ks++) {
                const int pp = ks & 1;
                if (ks < 3) {
                    const int np = pp ^ 1, off = (ks + 1) * 32;
                    ldmatrix_x4(a[np][0], aW + off);
                    ldmatrix_x4(a[np][1], aW + 16 * ROWB + off);
                    ldmatrix_x4(b[np][0], bW + off);
                    ldmatrix_x4(b[np][1], bW + 16 * ROWB + off);
                }
                mma_s8(acc[0][0], a[pp][0], b[pp][0] + 0);
                mma_s8(acc[0][1], a[pp][0], b[pp][0] + 2);
                mma_s8(acc[0][2], a[pp][0], b[pp][1] + 0);
                mma_s8(acc[0][3], a[pp][0], b[pp][1] + 2);
                mma_s8(acc[1][0], a[pp][1], b[pp][0] + 0);
                mma_s8(acc[1][1], a[pp][1], b[pp][0] + 2);
                mma_s8(acc[1][2], a[pp][1], b[pp][1] + 0);
                mma_s8(acc[1][3], a[pp][1], b[pp][1] + 2);
            }

            if (last_k) {
                float rowC[2][2], colC[4][2];
#pragma unroll
                for (int i = 0; i < 2; i++) {
                    int r = m0 + wm + i * 16 + rr;
                    rowC[i][0] = Crow * g_rowsum[r]     + Cconst;
                    rowC[i][1] = Crow * g_rowsum[r + 8] + Cconst;
                }
#pragma unroll
                for (int j = 0; j < 4; j++) {
                    int c = n0 + wn + j * 8 + cc;
                    colC[j][0] = Ccol * g_colsum[c];
                    colC[j][1] = Ccol * g_colsum[c + 1];
                }
#pragma unroll
                for (int i = 0; i < 2; i++) {
#pragma unroll
                    for (int j = 0; j < 4; j++) {
                        size_t r = (size_t)(m0 + wm + i * 16 + rr);
                        size_t c = (size_t)(n0 + wn + j * 8 + cc);
                        float2 v0, v1;
                        v0.x = Sc * (float)acc[i][j][0] + rowC[i][0] + colC[j][0];
                        v0.y = Sc * (float)acc[i][j][1] + rowC[i][0] + colC[j][1];
                        v1.x = Sc * (float)acc[i][j][2] + rowC[i][1] + colC[j][0];
                        v1.y = Sc * (float)acc[i][j][3] + rowC[i][1] + colC[j][1];
                        *(float2*)(out + r * MDIM + c)       = v0;
                        *(float2*)(out + (r + 8) * MDIM + c) = v1;
#pragma unroll
                        for (int v = 0; v < 4; v++) acc[i][j][v] = 0;
                    }
                }
            }
        } else {
            // ------------ dp4a path: 32 rows x 32 cols x k128 -----------
            const char* sA = smem + (g & 3) * STAGE_BYTES;
            const char* sB = sA + A_STAGE + (BN_T + colblk) * ROWB;
            const int rbase = (dwid & 3) * 32 + rg;
#pragma unroll 2
            for (int kk = 0; kk < 8; kk++) {
                int4 av[4], bv[8];
#pragma unroll
                for (int i = 0; i < 4; i++)
                    av[i] = *(const int4*)(sA + (rbase + 8 * i) * ROWB + kk * 16);
#pragma unroll
                for (int j = 0; j < 8; j++)
                    bv[j] = *(const int4*)(sB + (cg + 4 * j) * ROWB + kk * 16);
#pragma unroll
                for (int i = 0; i < 4; i++)
#pragma unroll
                    for (int j = 0; j < 8; j++) {
                        int s = dacc[i][j];
                        s = __dp4a(av[i].x, bv[j].x, s);
                        s = __dp4a(av[i].y, bv[j].y, s);
                        s = __dp4a(av[i].z, bv[j].z, s);
                        s = __dp4a(av[i].w, bv[j].w, s);
                        dacc[i][j] = s;
                    }
            }

            if (last_k) {
#pragma unroll
                for (int i = 0; i < 4; i++) {
                    int r = m0 + (dwid & 3) * 32 + rg + 8 * i;
                    float rc = Crow * g_rowsum[r] + Cconst;
#pragma unroll
                    for (int j = 0; j < 8; j++) {
                        int c = n0 + BN_T + colblk + cg + 4 * j;
                        out[(size_t)r * MDIM + c] =
                            Sc * (float)dacc[i][j] + rc + Ccol * g_colsum[c];
                        dacc[i][j] = 0;
                    }
                }
            }
        }
    }
}

// ---------------------------------------------------------------------------
// Launch
// ---------------------------------------------------------------------------
extern "C" void kernel_launch(void* const* d_in, const int* in_sizes, int n_in,
                              void* d_out, int out_size) {
    const float* x = (const float*)d_in[0];  // [M,K]
    const float* y = (const float*)d_in[1];  // [K,N]
    float* out = (float*)d_out;

    static int nworkers = 0;
    if (nworkers == 0) {
        int dev = 0, sms = 148;
        cudaGetDevice(&dev);
        cudaDeviceGetAttribute(&sms, cudaDevAttrMultiProcessorCount, dev);
        nworkers = sms;  // 1 CTA/SM (smem 144KB)
        cudaFuncSetAttribute(gemm_kernel,
                             cudaFuncAttributeMaxDynamicSharedMemorySize,
                             SMEM_TOTAL);
    }

    void* csym = nullptr;
    cudaGetSymbolAddress(&csym, g_colsum);
    cudaMemsetAsync(csym, 0, MDIM * sizeof(float), 0);

    convert_x_kernel<<<MDIM, 256>>>(x);
    transpose_y_kernel<<<dim3(MDIM / 64, MDIM / 64), 256>>>(y);
    gemm_kernel<<<nworkers, 512, SMEM_TOTAL>>>(out, nworkers);
}